// round 2
// baseline (speedup 1.0000x reference)
#include <cuda_runtime.h>
#include <math.h>

#define SS 128
#define BB 64
#define VV 32000
#define EHH 512
#define EOO 512
#define HH 1024
#define G3 3072
#define TOK (SS*BB)   // 8192

// ---------------- scratch (no allocations allowed) ----------------
__device__ float g_emb[TOK*EHH];    // 16 MB
__device__ float g_x[TOK*EOO];      // 16 MB
__device__ float g_xw[(size_t)TOK*G3];   // 96 MB
__device__ float g_h[2][BB*HH];     // 0.5 MB

// ---------------- 1) embedding gather + bias + threshold ----------------
__global__ void emb_kernel(const int* __restrict__ ids,
                           const float* __restrict__ W1,
                           const float* __restrict__ b1)
{
    int tok = blockIdx.x;           // 0..8191  (= s*64 + b)
    int id  = ids[tok];
    for (int e = threadIdx.x; e < EHH; e += blockDim.x) {
        float v = W1[(size_t)e * VV + id] + b1[e];
        g_emb[(size_t)tok * EHH + e] = (v > 1e-6f) ? v : 0.0f;
    }
}

// ---------------- 2) tiled SGEMM: C = act(A @ Bw^T + bias) ----------------
// A [M,K] row-major, Bw [N,K] row-major. Tile 128x128, BK=8, 256 thr, 8x8 micro.
template<int ACT>
__global__ void __launch_bounds__(256)
gemm_nt_act(const float* __restrict__ A, const float* __restrict__ Bw,
            const float* __restrict__ bias, float* __restrict__ C,
            int M, int N, int K)
{
    __shared__ float As[8][132];
    __shared__ float Bs[8][132];
    const int tid = threadIdx.x;
    const int bm = blockIdx.y * 128;
    const int bn = blockIdx.x * 128;
    const int lr = tid >> 1;            // 0..127
    const int lc = (tid & 1) * 4;       // 0 or 4
    const int ty = tid >> 4;            // 0..15
    const int tx = tid & 15;            // 0..15

    float acc[8][8];
    #pragma unroll
    for (int i = 0; i < 8; i++)
        #pragma unroll
        for (int j = 0; j < 8; j++) acc[i][j] = 0.0f;

    const float* Ap = A  + (size_t)(bm + lr) * K + lc;
    const float* Bp = Bw + (size_t)(bn + lr) * K + lc;

    for (int k0 = 0; k0 < K; k0 += 8) {
        float4 av = *(const float4*)(Ap + k0);
        float4 bv = *(const float4*)(Bp + k0);
        As[lc+0][lr] = av.x; As[lc+1][lr] = av.y;
        As[lc+2][lr] = av.z; As[lc+3][lr] = av.w;
        Bs[lc+0][lr] = bv.x; Bs[lc+1][lr] = bv.y;
        Bs[lc+2][lr] = bv.z; Bs[lc+3][lr] = bv.w;
        __syncthreads();
        #pragma unroll
        for (int kk = 0; kk < 8; kk++) {
            float4 a0 = *(const float4*)&As[kk][ty*8];
            float4 a1 = *(const float4*)&As[kk][ty*8+4];
            float4 b0 = *(const float4*)&Bs[kk][tx*8];
            float4 b1v = *(const float4*)&Bs[kk][tx*8+4];
            float af[8] = {a0.x,a0.y,a0.z,a0.w,a1.x,a1.y,a1.z,a1.w};
            float bf[8] = {b0.x,b0.y,b0.z,b0.w,b1v.x,b1v.y,b1v.z,b1v.w};
            #pragma unroll
            for (int i = 0; i < 8; i++)
                #pragma unroll
                for (int j = 0; j < 8; j++)
                    acc[i][j] += af[i] * bf[j];
        }
        __syncthreads();
    }

    #pragma unroll
    for (int i = 0; i < 8; i++) {
        int m = bm + ty*8 + i;
        float* Crow = C + (size_t)m * N + bn + tx*8;
        #pragma unroll
        for (int j = 0; j < 8; j++) {
            float v = acc[i][j] + bias[bn + tx*8 + j];
            if (ACT) v = (v > 1e-6f) ? v : 0.0f;
            Crow[j] = v;
        }
    }
}

// ---------------- 3) zero h0 ----------------
__global__ void zero_h_kernel()
{
    int i = blockIdx.x * blockDim.x + threadIdx.x;   // 64*256 = 16384 float4
    ((float4*)g_h[0])[i] = make_float4(0.f, 0.f, 0.f, 0.f);
}

// ---------------- 4) fused GRU step ----------------
// grid = 128 blocks (8 h-columns each, all 64 batches), 256 threads.
// Block computes gh tile [64 batches x 24 gate-rows] (rows j, H+j, 2H+j for
// j in [j0, j0+8)), with 4-way K-split across thread groups, then fuses
// the gate nonlinearities and h update.
__global__ void __launch_bounds__(256)
gru_step_kernel(const float* __restrict__ W_hh, const float* __restrict__ b_hh,
                const float* __restrict__ h_in, float* __restrict__ h_out,
                const float* __restrict__ xw_s /* [B, 3H] for this step */)
{
    __shared__ float Hs[4][16][68];   // [kgroup][k][batch]
    __shared__ float Ws[4][16][28];   // [kgroup][k][gaterow]
    __shared__ float red[64][25];     // gh tile reduction

    const int tid = threadIdx.x;
    const int g   = tid >> 6;         // k-group 0..3
    const int t   = tid & 63;
    const int tb  = t >> 3;           // batch-group 0..7 -> batches tb*8+i
    const int tc  = t & 7;            // col-group 0..7 -> cols tc*3+j
    const int j0  = blockIdx.x * 8;

    // zero the reduction tile
    for (int f = tid; f < 64*25; f += 256) ((float*)red)[f] = 0.0f;

    float acc[8][3];
    #pragma unroll
    for (int i = 0; i < 8; i++) { acc[i][0]=0.f; acc[i][1]=0.f; acc[i][2]=0.f; }

    const int kstart = g * 256;       // each group covers 256 k, in 16 tiles of 16

    for (int kt = 0; kt < 16; kt++) {
        const int kbase = kstart + kt * 16;
        __syncthreads();
        // load H tile: 64 batches x 16 k = 256 float4 per group
        #pragma unroll
        for (int r = 0; r < 4; r++) {
            int f = t + 64*r;             // 0..255
            int b = f >> 2;               // 0..63
            int q = f & 3;                // float4 index over k
            float4 hv = *(const float4*)&h_in[(size_t)b*HH + kbase + q*4];
            Hs[g][q*4+0][b] = hv.x; Hs[g][q*4+1][b] = hv.y;
            Hs[g][q*4+2][b] = hv.z; Hs[g][q*4+3][b] = hv.w;
        }
        // load W tile: 24 rows x 16 k = 96 float4 per group
        #pragma unroll
        for (int r = 0; r < 2; r++) {
            int f = t + 64*r;
            if (f < 96) {
                int c = f >> 2;           // 0..23
                int q = f & 3;
                int grow = (c >> 3) * HH + j0 + (c & 7);
                float4 wv = *(const float4*)&W_hh[(size_t)grow*HH + kbase + q*4];
                Ws[g][q*4+0][c] = wv.x; Ws[g][q*4+1][c] = wv.y;
                Ws[g][q*4+2][c] = wv.z; Ws[g][q*4+3][c] = wv.w;
            }
        }
        __syncthreads();
        #pragma unroll
        for (int k = 0; k < 16; k++) {
            float4 h0 = *(const float4*)&Hs[g][k][tb*8];
            float4 h1 = *(const float4*)&Hs[g][k][tb*8+4];
            float hf[8] = {h0.x,h0.y,h0.z,h0.w,h1.x,h1.y,h1.z,h1.w};
            float w0 = Ws[g][k][tc*3+0];
            float w1 = Ws[g][k][tc*3+1];
            float w2 = Ws[g][k][tc*3+2];
            #pragma unroll
            for (int i = 0; i < 8; i++) {
                acc[i][0] += hf[i]*w0;
                acc[i][1] += hf[i]*w1;
                acc[i][2] += hf[i]*w2;
            }
        }
    }

    // deterministic 4-way reduction into red (groups take turns)
    for (int gg = 0; gg < 4; gg++) {
        __syncthreads();
        if (g == gg) {
            #pragma unroll
            for (int i = 0; i < 8; i++)
                #pragma unroll
                for (int j = 0; j < 3; j++) {
                    int b = tb*8 + i, c = tc*3 + j;
                    if (gg == 0) red[b][c] = acc[i][j];
                    else         red[b][c] += acc[i][j];
                }
        }
    }
    __syncthreads();

    // gate math + h update: 512 (b, jj) pairs
    for (int p = tid; p < 512; p += 256) {
        int b  = p >> 3;
        int jj = p & 7;
        int j  = j0 + jj;
        float ghr = red[b][jj]      + b_hh[j];
        float ghz = red[b][8+jj]    + b_hh[HH + j];
        float ghn = red[b][16+jj]   + b_hh[2*HH + j];
        const float* xwb = xw_s + (size_t)b * G3;
        float xr = xwb[j];
        float xz = xwb[HH + j];
        float xn = xwb[2*HH + j];
        float r = 1.0f / (1.0f + expf(-(xr + ghr)));
        float z = 1.0f / (1.0f + expf(-(xz + ghz)));
        float n = tanhf(xn + r * ghn);
        float hp = h_in[(size_t)b*HH + j];
        h_out[(size_t)b*HH + j] = (1.0f - z) * n + z * hp;
    }
}

// ---------------- 5) final linear: out = hT @ W_out^T + b_out ----------------
// grid (8 batch-groups, 128 n-groups), 256 threads: warp per n, 8 batches each.
__global__ void __launch_bounds__(256)
out_kernel(const float* __restrict__ h, const float* __restrict__ Wo,
           const float* __restrict__ bo, float* __restrict__ out)
{
    __shared__ float hs[8][1024];
    const int b0 = blockIdx.x * 8;
    const int n0 = blockIdx.y * 8;
    const int tid = threadIdx.x;

    #pragma unroll
    for (int r = 0; r < 8; r++) {
        int f = tid + 256*r;              // 0..2047 float4
        int bb = f >> 8;
        int k4 = f & 255;
        *(float4*)&hs[bb][k4*4] = *(const float4*)&h[(size_t)(b0+bb)*HH + k4*4];
    }
    __syncthreads();

    const int w = tid >> 5, lane = tid & 31;
    const int n = n0 + w;
    float acc[8] = {0,0,0,0,0,0,0,0};
    for (int k = lane*4; k < 1024; k += 128) {
        float4 wv = *(const float4*)&Wo[(size_t)n*HH + k];
        #pragma unroll
        for (int bb = 0; bb < 8; bb++) {
            float4 hv = *(const float4*)&hs[bb][k];
            acc[bb] += wv.x*hv.x + wv.y*hv.y + wv.z*hv.z + wv.w*hv.w;
        }
    }
    #pragma unroll
    for (int bb = 0; bb < 8; bb++) {
        float v = acc[bb];
        v += __shfl_down_sync(0xffffffffu, v, 16);
        v += __shfl_down_sync(0xffffffffu, v, 8);
        v += __shfl_down_sync(0xffffffffu, v, 4);
        v += __shfl_down_sync(0xffffffffu, v, 2);
        v += __shfl_down_sync(0xffffffffu, v, 1);
        if (lane == 0) out[(size_t)(b0+bb)*1024 + n] = v + bo[n];
    }
}

// ---------------- launch ----------------
extern "C" void kernel_launch(void* const* d_in, const int* in_sizes, int n_in,
                              void* d_out, int out_size)
{
    const int*   ids   = (const int*)  d_in[0];
    const float* W1    = (const float*)d_in[1];
    const float* b1    = (const float*)d_in[2];
    const float* W2    = (const float*)d_in[3];
    const float* b2    = (const float*)d_in[4];
    const float* W_ih  = (const float*)d_in[5];
    const float* b_ih  = (const float*)d_in[6];
    const float* W_hh  = (const float*)d_in[7];
    const float* b_hh  = (const float*)d_in[8];
    const float* W_out = (const float*)d_in[9];
    const float* b_out = (const float*)d_in[10];
    float* out = (float*)d_out;

    float* emb; cudaGetSymbolAddress((void**)&emb, g_emb);
    float* x;   cudaGetSymbolAddress((void**)&x,   g_x);
    float* xw;  cudaGetSymbolAddress((void**)&xw,  g_xw);
    float* hbuf;cudaGetSymbolAddress((void**)&hbuf,g_h);

    emb_kernel<<<TOK, 128>>>(ids, W1, b1);

    // x = thresh(emb @ W2^T + b2)   [8192,512] x [512,512]
    gemm_nt_act<1><<<dim3(EOO/128, TOK/128), 256>>>(emb, W2, b2, x, TOK, EOO, EHH);

    // xW = x @ W_ih^T + b_ih        [8192,512] x [3072,512]
    gemm_nt_act<0><<<dim3(G3/128, TOK/128), 256>>>(x, W_ih, b_ih, xw, TOK, G3, EOO);

    zero_h_kernel<<<64, 256>>>();

    for (int s = 0; s < SS; s++) {
        const float* h_in  = hbuf + (s & 1) * (BB*HH);
        float*       h_out = hbuf + ((s + 1) & 1) * (BB*HH);
        gru_step_kernel<<<HH/8, 256>>>(W_hh, b_hh, h_in, h_out,
                                       xw + (size_t)s * BB * G3);
    }

    // final h is in g_h[0] (after 128 steps)
    out_kernel<<<dim3(8, 128), 256>>>(hbuf, W_out, b_out, out);
}

// round 3
// speedup vs baseline: 1.1720x; 1.1720x over previous
#include <cuda_runtime.h>
#include <math.h>

#define SS 128
#define BB 64
#define VV 32000
#define EHH 512
#define EOO 512
#define HH 1024
#define G3 3072
#define TOK (SS*BB)   // 8192
#define NB 128        // persistent blocks
#define NT 256

// ---------------- scratch (no allocations allowed) ----------------
__device__ float g_emb[TOK*EHH];          // 16 MB
__device__ float g_x[TOK*EOO];            // 16 MB
__device__ float g_xw[(size_t)TOK*G3];    // 96 MB
__device__ float g_h[2][BB*HH];           // 0.5 MB
__device__ unsigned g_count;              // grid barrier
__device__ volatile unsigned g_gen;

// ---------------- f32x2 helpers (sm_103a packed fp32 FMA) ----------------
__device__ __forceinline__ unsigned long long ffma2(unsigned long long a,
                                                    unsigned long long b,
                                                    unsigned long long c)
{
    unsigned long long d;
    asm("fma.rn.f32x2 %0, %1, %2, %3;" : "=l"(d) : "l"(a), "l"(b), "l"(c));
    return d;
}
__device__ __forceinline__ unsigned long long splat2(float x)
{
    unsigned long long d;
    asm("mov.b64 %0, {%1, %1};" : "=l"(d) : "r"(__float_as_uint(x)));
    return d;
}
__device__ __forceinline__ float2 unpack2(unsigned long long v)
{
    float2 r;
    asm("mov.b64 {%0, %1}, %2;" : "=f"(r.x), "=f"(r.y) : "l"(v));
    return r;
}

// ---------------- 1) embedding gather + bias + threshold ----------------
__global__ void emb_kernel(const int* __restrict__ ids,
                           const float* __restrict__ W1,
                           const float* __restrict__ b1)
{
    int tok = blockIdx.x;
    int id  = ids[tok];
    for (int e = threadIdx.x; e < EHH; e += blockDim.x) {
        float v = W1[(size_t)e * VV + id] + b1[e];
        g_emb[(size_t)tok * EHH + e] = (v > 1e-6f) ? v : 0.0f;
    }
}

// ---------------- 2) tiled SGEMM (f32x2): C = act(A @ Bw^T + bias) --------
// A [M,K] row-major, Bw [N,K] row-major. Tile 128x128, BK=8, 256 thr, 8x8.
template<int ACT>
__global__ void __launch_bounds__(256)
gemm_nt_act(const float* __restrict__ A, const float* __restrict__ Bw,
            const float* __restrict__ bias, float* __restrict__ C,
            int M, int N, int K)
{
    __shared__ float As[8][132];
    __shared__ float Bs[8][132];
    const int tid = threadIdx.x;
    const int bm = blockIdx.y * 128;
    const int bn = blockIdx.x * 128;
    const int lr = tid >> 1;
    const int lc = (tid & 1) * 4;
    const int ty = tid >> 4;
    const int tx = tid & 15;

    unsigned long long acc2[4][8];
    #pragma unroll
    for (int i = 0; i < 4; i++)
        #pragma unroll
        for (int j = 0; j < 8; j++) acc2[i][j] = 0ULL;

    const float* Ap = A  + (size_t)(bm + lr) * K + lc;
    const float* Bp = Bw + (size_t)(bn + lr) * K + lc;

    for (int k0 = 0; k0 < K; k0 += 8) {
        float4 av = *(const float4*)(Ap + k0);
        float4 bv = *(const float4*)(Bp + k0);
        As[lc+0][lr] = av.x; As[lc+1][lr] = av.y;
        As[lc+2][lr] = av.z; As[lc+3][lr] = av.w;
        Bs[lc+0][lr] = bv.x; Bs[lc+1][lr] = bv.y;
        Bs[lc+2][lr] = bv.z; Bs[lc+3][lr] = bv.w;
        __syncthreads();
        #pragma unroll
        for (int kk = 0; kk < 8; kk++) {
            ulonglong2 A01 = *(const ulonglong2*)&As[kk][ty*8];
            ulonglong2 A23 = *(const ulonglong2*)&As[kk][ty*8+4];
            float4 b0 = *(const float4*)&Bs[kk][tx*8];
            float4 b1 = *(const float4*)&Bs[kk][tx*8+4];
            unsigned long long a2[4] = {A01.x, A01.y, A23.x, A23.y};
            unsigned long long bsp[8] = {
                splat2(b0.x), splat2(b0.y), splat2(b0.z), splat2(b0.w),
                splat2(b1.x), splat2(b1.y), splat2(b1.z), splat2(b1.w)};
            #pragma unroll
            for (int i2 = 0; i2 < 4; i2++)
                #pragma unroll
                for (int j = 0; j < 8; j++)
                    acc2[i2][j] = ffma2(a2[i2], bsp[j], acc2[i2][j]);
        }
        __syncthreads();
    }

    #pragma unroll
    for (int i2 = 0; i2 < 4; i2++) {
        int m0 = bm + ty*8 + i2*2;
        #pragma unroll
        for (int j = 0; j < 8; j++) {
            float2 v = unpack2(acc2[i2][j]);
            float bb = bias[bn + tx*8 + j];
            float v0 = v.x + bb, v1 = v.y + bb;
            if (ACT) { v0 = (v0 > 1e-6f) ? v0 : 0.0f;
                       v1 = (v1 > 1e-6f) ? v1 : 0.0f; }
            C[(size_t)m0     * N + bn + tx*8 + j] = v0;
            C[(size_t)(m0+1) * N + bn + tx*8 + j] = v1;
        }
    }
}

// ---------------- grid barrier (sense-reversing, graph-replay safe) -------
__device__ __forceinline__ void grid_bar()
{
    __threadfence();
    __syncthreads();
    if (threadIdx.x == 0) {
        unsigned my = g_gen;
        if (atomicAdd(&g_count, 1) == gridDim.x - 1) {
            g_count = 0;
            __threadfence();
            g_gen = my + 1;
        } else {
            while (g_gen == my) { }
        }
    }
    __syncthreads();
}

// ---------------- 3) persistent GRU recurrence ----------------------------
// 128 blocks, 256 threads, 1 block/SM (smem-limited -> guaranteed wave-1
// residency). Block owns 8 h-columns (j0..j0+7) = 24 W_hh rows cached in
// smem for all 128 steps. Per step: 64x24x1024 GEMM with 4-way K split,
// double-buffered h staging via L2 (__ldcg), f32x2 FMAs, fused gates.
#define WSM_F   (1024*25)          // Wsm[k*25 + c], c in [0,24)
#define HSS_F   (2*4*16*72)        // Hs[buf][g][k][b(+pad)]
#define RED_F   (64*25)
#define SMEM_BYTES ((WSM_F + HSS_F + RED_F) * 4)

__global__ void __launch_bounds__(NT, 1)
gru_persist(const float* __restrict__ W_hh, const float* __restrict__ b_hh,
            const float* __restrict__ xw, float* __restrict__ hbuf)
{
    extern __shared__ float smf[];
    float* Wsm = smf;                    // 25600 floats
    float* Hss = smf + WSM_F;            // 9216 floats
    float* red = smf + WSM_F + HSS_F;    // 1600 floats

    const int tid = threadIdx.x;
    const int g   = tid >> 6;            // k-group 0..3
    const int t   = tid & 63;
    const int tb  = t >> 3;              // batch-group 0..7
    const int tc  = t & 7;               // c-group 0..7 (c = tc*3+j)
    const int j0  = blockIdx.x * 8;

    // cache W_hh slice: Wsm[k*25 + c] = W_hh[(c>>3)*H + j0 + (c&7)][k]
    for (int idx = tid; idx < 24*1024; idx += NT) {
        int c = idx >> 10, k = idx & 1023;
        int grow = (c >> 3) * HH + j0 + (c & 7);
        Wsm[k*25 + c] = W_hh[(size_t)grow * HH + k];
    }

    // gate-phase thread mapping (each thread handles batches bb0, bb0+32)
    const int bb0  = tid >> 3;
    const int bb1  = bb0 + 32;
    const int jj   = tid & 7;
    const int jcol = j0 + jj;
    const float bhr = b_hh[jcol];
    const float bhz = b_hh[HH + jcol];
    const float bhn = b_hh[2*HH + jcol];
    __syncthreads();

    for (int s = 0; s < SS; s++) {
        const float* h_in  = hbuf + (s & 1) * (BB*HH);
        float*       h_out = hbuf + ((s + 1) & 1) * (BB*HH);
        const float* xws   = xw + (size_t)s * BB * G3;

        // prefetch gate inputs early (hidden under the GEMM)
        float xr0 = __ldg(&xws[(size_t)bb0*G3 + jcol]);
        float xz0 = __ldg(&xws[(size_t)bb0*G3 + HH  + jcol]);
        float xn0 = __ldg(&xws[(size_t)bb0*G3 + 2*HH + jcol]);
        float xr1 = __ldg(&xws[(size_t)bb1*G3 + jcol]);
        float xz1 = __ldg(&xws[(size_t)bb1*G3 + HH  + jcol]);
        float xn1 = __ldg(&xws[(size_t)bb1*G3 + 2*HH + jcol]);
        float hp0 = 0.f, hp1 = 0.f;
        float gr0 = 0.f, gz0 = 0.f, gn0 = 0.f;
        float gr1 = 0.f, gz1 = 0.f, gn1 = 0.f;

        if (s > 0) {
            hp0 = __ldcg(&h_in[(size_t)bb0*HH + jcol]);
            hp1 = __ldcg(&h_in[(size_t)bb1*HH + jcol]);

            unsigned long long acc2[4][3];
            #pragma unroll
            for (int i = 0; i < 4; i++)
                #pragma unroll
                for (int j = 0; j < 3; j++) acc2[i][j] = 0ULL;

            // prologue: prefetch kt=0 tile into regs (L2 reads)
            float4 pre[4];
            {
                int kb = g * 256;
                #pragma unroll
                for (int r = 0; r < 4; r++) {
                    int f = t + 64*r, b = f >> 2, q = f & 3;
                    pre[r] = __ldcg((const float4*)&h_in[(size_t)b*HH + kb + q*4]);
                }
            }

            for (int kt = 0; kt < 16; kt++) {
                float* Hbuf = Hss + (((kt & 1) * 4 + g) * 16) * 72;
                // store prefetched tile
                #pragma unroll
                for (int r = 0; r < 4; r++) {
                    int f = t + 64*r, b = f >> 2, q = f & 3;
                    float4 v = pre[r];
                    Hbuf[(q*4+0)*72 + b] = v.x;
                    Hbuf[(q*4+1)*72 + b] = v.y;
                    Hbuf[(q*4+2)*72 + b] = v.z;
                    Hbuf[(q*4+3)*72 + b] = v.w;
                }
                __syncthreads();
                // prefetch next tile (hidden under compute)
                if (kt < 15) {
                    int kb = g * 256 + (kt + 1) * 16;
                    #pragma unroll
                    for (int r = 0; r < 4; r++) {
                        int f = t + 64*r, b = f >> 2, q = f & 3;
                        pre[r] = __ldcg((const float4*)&h_in[(size_t)b*HH + kb + q*4]);
                    }
                }
                const float* wbase = Wsm + (g*256 + kt*16) * 25 + tc*3;
                #pragma unroll
                for (int kk = 0; kk < 16; kk++) {
                    const float* hrow = Hbuf + kk*72;
                    ulonglong2 hA = *(const ulonglong2*)&hrow[tb*8];
                    ulonglong2 hB = *(const ulonglong2*)&hrow[tb*8 + 4];
                    const float* wr = wbase + kk*25;
                    unsigned long long w0 = splat2(wr[0]);
                    unsigned long long w1 = splat2(wr[1]);
                    unsigned long long w2 = splat2(wr[2]);
                    acc2[0][0] = ffma2(hA.x, w0, acc2[0][0]);
                    acc2[0][1] = ffma2(hA.x, w1, acc2[0][1]);
                    acc2[0][2] = ffma2(hA.x, w2, acc2[0][2]);
                    acc2[1][0] = ffma2(hA.y, w0, acc2[1][0]);
                    acc2[1][1] = ffma2(hA.y, w1, acc2[1][1]);
                    acc2[1][2] = ffma2(hA.y, w2, acc2[1][2]);
                    acc2[2][0] = ffma2(hB.x, w0, acc2[2][0]);
                    acc2[2][1] = ffma2(hB.x, w1, acc2[2][1]);
                    acc2[2][2] = ffma2(hB.x, w2, acc2[2][2]);
                    acc2[3][0] = ffma2(hB.y, w0, acc2[3][0]);
                    acc2[3][1] = ffma2(hB.y, w1, acc2[3][1]);
                    acc2[3][2] = ffma2(hB.y, w2, acc2[3][2]);
                }
            }

            // deterministic 4-way k-group reduction
            for (int gg = 0; gg < 4; gg++) {
                __syncthreads();
                if (g == gg) {
                    #pragma unroll
                    for (int i2 = 0; i2 < 4; i2++) {
                        int b = tb*8 + i2*2;
                        #pragma unroll
                        for (int j = 0; j < 3; j++) {
                            float2 v = unpack2(acc2[i2][j]);
                            int c = tc*3 + j;
                            if (gg == 0) { red[b*25 + c] = v.x; red[(b+1)*25 + c] = v.y; }
                            else         { red[b*25 + c] += v.x; red[(b+1)*25 + c] += v.y; }
                        }
                    }
                }
            }
            __syncthreads();
            gr0 = red[bb0*25 + jj];      gr1 = red[bb1*25 + jj];
            gz0 = red[bb0*25 + 8 + jj];  gz1 = red[bb1*25 + 8 + jj];
            gn0 = red[bb0*25 + 16 + jj]; gn1 = red[bb1*25 + 16 + jj];
        }

        // fused gates + h update
        {
            float r0 = 1.0f / (1.0f + __expf(-(xr0 + gr0 + bhr)));
            float z0 = 1.0f / (1.0f + __expf(-(xz0 + gz0 + bhz)));
            float n0 = tanhf(xn0 + r0 * (gn0 + bhn));
            __stcg(&h_out[(size_t)bb0*HH + jcol], (1.0f - z0) * n0 + z0 * hp0);

            float r1 = 1.0f / (1.0f + __expf(-(xr1 + gr1 + bhr)));
            float z1 = 1.0f / (1.0f + __expf(-(xz1 + gz1 + bhz)));
            float n1 = tanhf(xn1 + r1 * (gn1 + bhn));
            __stcg(&h_out[(size_t)bb1*HH + jcol], (1.0f - z1) * n1 + z1 * hp1);
        }

        grid_bar();
    }
}

// ---------------- 4) final linear: out = hT @ W_out^T + b_out -------------
__global__ void __launch_bounds__(256)
out_kernel(const float* __restrict__ h, const float* __restrict__ Wo,
           const float* __restrict__ bo, float* __restrict__ out)
{
    __shared__ float hs[8][1024];
    const int b0 = blockIdx.x * 8;
    const int n0 = blockIdx.y * 8;
    const int tid = threadIdx.x;

    #pragma unroll
    for (int r = 0; r < 8; r++) {
        int f = tid + 256*r;
        int bb = f >> 8;
        int k4 = f & 255;
        *(float4*)&hs[bb][k4*4] = *(const float4*)&h[(size_t)(b0+bb)*HH + k4*4];
    }
    __syncthreads();

    const int w = tid >> 5, lane = tid & 31;
    const int n = n0 + w;
    float acc[8] = {0,0,0,0,0,0,0,0};
    for (int k = lane*4; k < 1024; k += 128) {
        float4 wv = *(const float4*)&Wo[(size_t)n*HH + k];
        #pragma unroll
        for (int bb = 0; bb < 8; bb++) {
            float4 hv = *(const float4*)&hs[bb][k];
            acc[bb] += wv.x*hv.x + wv.y*hv.y + wv.z*hv.z + wv.w*hv.w;
        }
    }
    #pragma unroll
    for (int bb = 0; bb < 8; bb++) {
        float v = acc[bb];
        v += __shfl_down_sync(0xffffffffu, v, 16);
        v += __shfl_down_sync(0xffffffffu, v, 8);
        v += __shfl_down_sync(0xffffffffu, v, 4);
        v += __shfl_down_sync(0xffffffffu, v, 2);
        v += __shfl_down_sync(0xffffffffu, v, 1);
        if (lane == 0) out[(size_t)(b0+bb)*1024 + n] = v + bo[n];
    }
}

// ---------------- launch ----------------
extern "C" void kernel_launch(void* const* d_in, const int* in_sizes, int n_in,
                              void* d_out, int out_size)
{
    const int*   ids   = (const int*)  d_in[0];
    const float* W1    = (const float*)d_in[1];
    const float* b1    = (const float*)d_in[2];
    const float* W2    = (const float*)d_in[3];
    const float* b2    = (const float*)d_in[4];
    const float* W_ih  = (const float*)d_in[5];
    const float* b_ih  = (const float*)d_in[6];
    const float* W_hh  = (const float*)d_in[7];
    const float* b_hh  = (const float*)d_in[8];
    const float* W_out = (const float*)d_in[9];
    const float* b_out = (const float*)d_in[10];
    float* out = (float*)d_out;

    float* emb;  cudaGetSymbolAddress((void**)&emb,  g_emb);
    float* x;    cudaGetSymbolAddress((void**)&x,    g_x);
    float* xw;   cudaGetSymbolAddress((void**)&xw,   g_xw);
    float* hbuf; cudaGetSymbolAddress((void**)&hbuf, g_h);

    static int smem_set = 0;
    if (!smem_set) {
        cudaFuncSetAttribute(gru_persist,
                             cudaFuncAttributeMaxDynamicSharedMemorySize,
                             SMEM_BYTES);
        smem_set = 1;
    }

    emb_kernel<<<TOK, 128>>>(ids, W1, b1);

    gemm_nt_act<1><<<dim3(EOO/128, TOK/128), 256>>>(emb, W2, b2, x, TOK, EOO, EHH);
    gemm_nt_act<0><<<dim3(G3/128,  TOK/128), 256>>>(x, W_ih, b_ih, xw, TOK, G3, EOO);

    gru_persist<<<NB, NT, SMEM_BYTES>>>(W_hh, b_hh, xw, hbuf);

    out_kernel<<<dim3(8, 128), 256>>>(hbuf, W_out, b_out, out);
}

// round 4
// speedup vs baseline: 1.2771x; 1.0897x over previous
#include <cuda_runtime.h>
#include <math.h>

#define SS 128
#define BB 64
#define VV 32000
#define EHH 512
#define EOO 512
#define HH 1024
#define G3 3072
#define TOK (SS*BB)   // 8192
#define NB 128        // persistent blocks
#define GNT 512       // gru threads per block

// ---------------- scratch (no allocations allowed) ----------------
__device__ float g_emb[TOK*EHH];          // 16 MB
__device__ float g_x[TOK*EOO];            // 16 MB
__device__ float g_xw[(size_t)TOK*G3];    // 96 MB
__device__ float g_h[2][BB*HH];           // 0.5 MB
__device__ unsigned g_count;              // grid barrier
__device__ volatile unsigned g_gen;

// ---------------- f32x2 helpers (sm_103a packed fp32 FMA) ----------------
__device__ __forceinline__ unsigned long long ffma2(unsigned long long a,
                                                    unsigned long long b,
                                                    unsigned long long c)
{
    unsigned long long d;
    asm("fma.rn.f32x2 %0, %1, %2, %3;" : "=l"(d) : "l"(a), "l"(b), "l"(c));
    return d;
}
__device__ __forceinline__ unsigned long long splat2(float x)
{
    unsigned long long d;
    asm("mov.b64 %0, {%1, %1};" : "=l"(d) : "r"(__float_as_uint(x)));
    return d;
}
__device__ __forceinline__ float2 unpack2(unsigned long long v)
{
    float2 r;
    asm("mov.b64 {%0, %1}, %2;" : "=f"(r.x), "=f"(r.y) : "l"(v));
    return r;
}

// ---------------- 1) embedding gather + bias + threshold ----------------
__global__ void emb_kernel(const int* __restrict__ ids,
                           const float* __restrict__ W1,
                           const float* __restrict__ b1)
{
    int tok = blockIdx.x;
    int id  = ids[tok];
    for (int e = threadIdx.x; e < EHH; e += blockDim.x) {
        float v = W1[(size_t)e * VV + id] + b1[e];
        g_emb[(size_t)tok * EHH + e] = (v > 1e-6f) ? v : 0.0f;
    }
}

// ---------------- 2) tiled SGEMM (f32x2): C = act(A @ Bw^T + bias) --------
template<int ACT>
__global__ void __launch_bounds__(256)
gemm_nt_act(const float* __restrict__ A, const float* __restrict__ Bw,
            const float* __restrict__ bias, float* __restrict__ C,
            int M, int N, int K)
{
    __shared__ float As[8][132];
    __shared__ float Bs[8][132];
    const int tid = threadIdx.x;
    const int bm = blockIdx.y * 128;
    const int bn = blockIdx.x * 128;
    const int lr = tid >> 1;
    const int lc = (tid & 1) * 4;
    const int ty = tid >> 4;
    const int tx = tid & 15;

    unsigned long long acc2[4][8];
    #pragma unroll
    for (int i = 0; i < 4; i++)
        #pragma unroll
        for (int j = 0; j < 8; j++) acc2[i][j] = 0ULL;

    const float* Ap = A  + (size_t)(bm + lr) * K + lc;
    const float* Bp = Bw + (size_t)(bn + lr) * K + lc;

    for (int k0 = 0; k0 < K; k0 += 8) {
        float4 av = *(const float4*)(Ap + k0);
        float4 bv = *(const float4*)(Bp + k0);
        As[lc+0][lr] = av.x; As[lc+1][lr] = av.y;
        As[lc+2][lr] = av.z; As[lc+3][lr] = av.w;
        Bs[lc+0][lr] = bv.x; Bs[lc+1][lr] = bv.y;
        Bs[lc+2][lr] = bv.z; Bs[lc+3][lr] = bv.w;
        __syncthreads();
        #pragma unroll
        for (int kk = 0; kk < 8; kk++) {
            ulonglong2 A01 = *(const ulonglong2*)&As[kk][ty*8];
            ulonglong2 A23 = *(const ulonglong2*)&As[kk][ty*8+4];
            float4 b0 = *(const float4*)&Bs[kk][tx*8];
            float4 b1 = *(const float4*)&Bs[kk][tx*8+4];
            unsigned long long a2[4] = {A01.x, A01.y, A23.x, A23.y};
            unsigned long long bsp[8] = {
                splat2(b0.x), splat2(b0.y), splat2(b0.z), splat2(b0.w),
                splat2(b1.x), splat2(b1.y), splat2(b1.z), splat2(b1.w)};
            #pragma unroll
            for (int i2 = 0; i2 < 4; i2++)
                #pragma unroll
                for (int j = 0; j < 8; j++)
                    acc2[i2][j] = ffma2(a2[i2], bsp[j], acc2[i2][j]);
        }
        __syncthreads();
    }

    #pragma unroll
    for (int i2 = 0; i2 < 4; i2++) {
        int m0 = bm + ty*8 + i2*2;
        #pragma unroll
        for (int j = 0; j < 8; j++) {
            float2 v = unpack2(acc2[i2][j]);
            float bb = bias[bn + tx*8 + j];
            float v0 = v.x + bb, v1 = v.y + bb;
            if (ACT) { v0 = (v0 > 1e-6f) ? v0 : 0.0f;
                       v1 = (v1 > 1e-6f) ? v1 : 0.0f; }
            C[(size_t)m0     * N + bn + tx*8 + j] = v0;
            C[(size_t)(m0+1) * N + bn + tx*8 + j] = v1;
        }
    }
}

// ---------------- grid barrier (sense-reversing, graph-replay safe) -------
__device__ __forceinline__ void grid_bar()
{
    __threadfence();
    __syncthreads();
    if (threadIdx.x == 0) {
        unsigned my = g_gen;
        if (atomicAdd(&g_count, 1) == gridDim.x - 1) {
            g_count = 0;
            __threadfence();
            g_gen = my + 1;
        } else {
            while (g_gen == my) { }
        }
    }
    __syncthreads();
}

// ---------------- 3) persistent GRU recurrence ----------------------------
// 128 blocks x 512 threads, 1 block/SM (smem-limited). Block owns 8
// h-columns = 24 W_hh rows cached in smem for all 128 steps. Per step:
// 64x24x1024 GEMM with 8-way K split (64-thread groups, 8 k-tiles of 16
// each, double-buffered L2->smem staging), f32x2 FMAs, single parallel
// tree reduction (partials alias the H staging buffers), fused gates.
#define WSM_F   (1024*25)          // Wsm[k*25 + c], c in [0,24)
#define HSS_F   (2*8*16*68)        // Hs[buf][g][k][b] = 17408 floats
#define SMEM_BYTES ((WSM_F + HSS_F) * 4)   // 172032 B

__global__ void __launch_bounds__(GNT, 1)
gru_persist(const float* __restrict__ W_hh, const float* __restrict__ b_hh,
            const float* __restrict__ xw, float* __restrict__ hbuf)
{
    extern __shared__ float smf[];
    float* Wsm = smf;                    // 25600 floats
    float* Hss = smf + WSM_F;            // 17408 floats
    float* red = Hss;                    // alias: 8*1600 = 12800 floats

    const int tid = threadIdx.x;
    const int g   = tid >> 6;            // k-group 0..7 (covers 128 k)
    const int t   = tid & 63;
    const int tb  = t >> 3;              // batch-group 0..7 (8 batches)
    const int tc  = t & 7;               // c-group 0..7 (c = tc*3+j)
    const int j0  = blockIdx.x * 8;

    // cache W_hh slice: Wsm[k*25 + c] = W_hh[(c>>3)*H + j0 + (c&7)][k]
    for (int idx = tid; idx < 24*1024; idx += GNT) {
        int c = idx >> 10, k = idx & 1023;
        int grow = (c >> 3) * HH + j0 + (c & 7);
        Wsm[k*25 + c] = W_hh[(size_t)grow * HH + k];
    }

    // gate-phase mapping: one (batch, col) per thread
    const int bb   = tid >> 3;           // 0..63
    const int jj   = tid & 7;
    const int jcol = j0 + jj;
    const float bhr = b_hh[jcol];
    const float bhz = b_hh[HH + jcol];
    const float bhn = b_hh[2*HH + jcol];
    __syncthreads();

    for (int s = 0; s < SS; s++) {
        const float* h_in  = hbuf + (s & 1) * (BB*HH);
        float*       h_out = hbuf + ((s + 1) & 1) * (BB*HH);
        const float* xws   = xw + (size_t)s * BB * G3;

        // prefetch gate inputs early (hidden under the GEMM)
        float xr = __ldg(&xws[(size_t)bb*G3 + jcol]);
        float xz = __ldg(&xws[(size_t)bb*G3 + HH  + jcol]);
        float xn = __ldg(&xws[(size_t)bb*G3 + 2*HH + jcol]);
        float hp = 0.f, gr = 0.f, gz = 0.f, gn = 0.f;

        if (s > 0) {
            hp = __ldcg(&h_in[(size_t)bb*HH + jcol]);

            unsigned long long acc2[4][3];
            #pragma unroll
            for (int i = 0; i < 4; i++)
                #pragma unroll
                for (int j = 0; j < 3; j++) acc2[i][j] = 0ULL;

            // prologue: prefetch kt=0 tile (L2 reads)
            float4 pre[4];
            {
                int kb = g * 128;
                #pragma unroll
                for (int r = 0; r < 4; r++) {
                    int f = t + 64*r, b = f >> 2, q = f & 3;
                    pre[r] = __ldcg((const float4*)&h_in[(size_t)b*HH + kb + q*4]);
                }
            }

            for (int kt = 0; kt < 8; kt++) {
                float* Hbuf = Hss + (((kt & 1) * 8 + g) * 16) * 68;
                #pragma unroll
                for (int r = 0; r < 4; r++) {
                    int f = t + 64*r, b = f >> 2, q = f & 3;
                    float4 v = pre[r];
                    Hbuf[(q*4+0)*68 + b] = v.x;
                    Hbuf[(q*4+1)*68 + b] = v.y;
                    Hbuf[(q*4+2)*68 + b] = v.z;
                    Hbuf[(q*4+3)*68 + b] = v.w;
                }
                __syncthreads();
                if (kt < 7) {
                    int kb = g * 128 + (kt + 1) * 16;
                    #pragma unroll
                    for (int r = 0; r < 4; r++) {
                        int f = t + 64*r, b = f >> 2, q = f & 3;
                        pre[r] = __ldcg((const float4*)&h_in[(size_t)b*HH + kb + q*4]);
                    }
                }
                const float* wbase = Wsm + (g*128 + kt*16) * 25 + tc*3;
                #pragma unroll
                for (int kk = 0; kk < 16; kk++) {
                    const float* hrow = Hbuf + kk*68;
                    ulonglong2 hA = *(const ulonglong2*)&hrow[tb*8];
                    ulonglong2 hB = *(const ulonglong2*)&hrow[tb*8 + 4];
                    const float* wr = wbase + kk*25;
                    unsigned long long w0 = splat2(wr[0]);
                    unsigned long long w1 = splat2(wr[1]);
                    unsigned long long w2 = splat2(wr[2]);
                    acc2[0][0] = ffma2(hA.x, w0, acc2[0][0]);
                    acc2[0][1] = ffma2(hA.x, w1, acc2[0][1]);
                    acc2[0][2] = ffma2(hA.x, w2, acc2[0][2]);
                    acc2[1][0] = ffma2(hA.y, w0, acc2[1][0]);
                    acc2[1][1] = ffma2(hA.y, w1, acc2[1][1]);
                    acc2[1][2] = ffma2(hA.y, w2, acc2[1][2]);
                    acc2[2][0] = ffma2(hB.x, w0, acc2[2][0]);
                    acc2[2][1] = ffma2(hB.x, w1, acc2[2][1]);
                    acc2[2][2] = ffma2(hB.x, w2, acc2[2][2]);
                    acc2[3][0] = ffma2(hB.y, w0, acc2[3][0]);
                    acc2[3][1] = ffma2(hB.y, w1, acc2[3][1]);
                    acc2[3][2] = ffma2(hB.y, w2, acc2[3][2]);
                }
            }

            // parallel 8-way tree reduction (partials alias Hss)
            __syncthreads();   // all H tiles consumed; Hss reusable
            {
                float* myred = red + g * 1600;
                #pragma unroll
                for (int i2 = 0; i2 < 4; i2++) {
                    int b = tb*8 + i2*2;
                    #pragma unroll
                    for (int j = 0; j < 3; j++) {
                        float2 v = unpack2(acc2[i2][j]);
                        int c = tc*3 + j;
                        myred[b*25 + c]     = v.x;
                        myred[(b+1)*25 + c] = v.y;
                    }
                }
            }
            __syncthreads();
            for (int o = tid; o < 1600; o += GNT) {
                float sum = red[o];
                #pragma unroll
                for (int gg = 1; gg < 8; gg++) sum += red[gg*1600 + o];
                red[o] = sum;
            }
            __syncthreads();
            gr = red[bb*25 + jj];
            gz = red[bb*25 + 8 + jj];
            gn = red[bb*25 + 16 + jj];
        }

        // fused gates + h update (one (b, j) per thread)
        {
            float r = 1.0f / (1.0f + __expf(-(xr + gr + bhr)));
            float z = 1.0f / (1.0f + __expf(-(xz + gz + bhz)));
            float n = tanhf(xn + r * (gn + bhn));
            __stcg(&h_out[(size_t)bb*HH + jcol], (1.0f - z) * n + z * hp);
        }

        grid_bar();
    }
}

// ---------------- 4) final linear: out = hT @ W_out^T + b_out -------------
__global__ void __launch_bounds__(256)
out_kernel(const float* __restrict__ h, const float* __restrict__ Wo,
           const float* __restrict__ bo, float* __restrict__ out)
{
    __shared__ float hs[8][1024];
    const int b0 = blockIdx.x * 8;
    const int n0 = blockIdx.y * 8;
    const int tid = threadIdx.x;

    #pragma unroll
    for (int r = 0; r < 8; r++) {
        int f = tid + 256*r;
        int bb = f >> 8;
        int k4 = f & 255;
        *(float4*)&hs[bb][k4*4] = *(const float4*)&h[(size_t)(b0+bb)*HH + k4*4];
    }
    __syncthreads();

    const int w = tid >> 5, lane = tid & 31;
    const int n = n0 + w;
    float acc[8] = {0,0,0,0,0,0,0,0};
    for (int k = lane*4; k < 1024; k += 128) {
        float4 wv = *(const float4*)&Wo[(size_t)n*HH + k];
        #pragma unroll
        for (int bb = 0; bb < 8; bb++) {
            float4 hv = *(const float4*)&hs[bb][k];
            acc[bb] += wv.x*hv.x + wv.y*hv.y + wv.z*hv.z + wv.w*hv.w;
        }
    }
    #pragma unroll
    for (int bb = 0; bb < 8; bb++) {
        float v = acc[bb];
        v += __shfl_down_sync(0xffffffffu, v, 16);
        v += __shfl_down_sync(0xffffffffu, v, 8);
        v += __shfl_down_sync(0xffffffffu, v, 4);
        v += __shfl_down_sync(0xffffffffu, v, 2);
        v += __shfl_down_sync(0xffffffffu, v, 1);
        if (lane == 0) out[(size_t)(b0+bb)*1024 + n] = v + bo[n];
    }
}

// ---------------- launch ----------------
extern "C" void kernel_launch(void* const* d_in, const int* in_sizes, int n_in,
                              void* d_out, int out_size)
{
    const int*   ids   = (const int*)  d_in[0];
    const float* W1    = (const float*)d_in[1];
    const float* b1    = (const float*)d_in[2];
    const float* W2    = (const float*)d_in[3];
    const float* b2    = (const float*)d_in[4];
    const float* W_ih  = (const float*)d_in[5];
    const float* b_ih  = (const float*)d_in[6];
    const float* W_hh  = (const float*)d_in[7];
    const float* b_hh  = (const float*)d_in[8];
    const float* W_out = (const float*)d_in[9];
    const float* b_out = (const float*)d_in[10];
    float* out = (float*)d_out;

    float* emb;  cudaGetSymbolAddress((void**)&emb,  g_emb);
    float* x;    cudaGetSymbolAddress((void**)&x,    g_x);
    float* xw;   cudaGetSymbolAddress((void**)&xw,   g_xw);
    float* hbuf; cudaGetSymbolAddress((void**)&hbuf, g_h);

    static int smem_set = 0;
    if (!smem_set) {
        cudaFuncSetAttribute(gru_persist,
                             cudaFuncAttributeMaxDynamicSharedMemorySize,
                             SMEM_BYTES);
        smem_set = 1;
    }

    emb_kernel<<<TOK, 128>>>(ids, W1, b1);

    gemm_nt_act<1><<<dim3(EOO/128, TOK/128), 256>>>(emb, W2, b2, x, TOK, EOO, EHH);
    gemm_nt_act<0><<<dim3(G3/128,  TOK/128), 256>>>(x, W_ih, b_ih, xw, TOK, G3, EOO);

    gru_persist<<<NB, GNT, SMEM_BYTES>>>(W_hh, b_hh, xw, hbuf);

    out_kernel<<<dim3(8, 128), 256>>>(hbuf, W_out, b_out, out);
}

// round 6
// speedup vs baseline: 1.3195x; 1.0332x over previous
#include <cuda_runtime.h>
#include <math.h>

#define SS 128
#define BB 64
#define VV 32000
#define EHH 512
#define EOO 512
#define HH 1024
#define G3 3072
#define TOK (SS*BB)   // 8192
#define NB 128        // persistent blocks
#define GNT 512       // gru threads per block

// ---------------- scratch (no allocations allowed) ----------------
__device__ float g_emb[TOK*EHH];          // 16 MB
__device__ float g_x[TOK*EOO];            // 16 MB
__device__ float g_xw[(size_t)TOK*G3];    // 96 MB
__device__ float g_h[2][HH*BB];           // transposed: h[j][b]
__device__ __align__(128) unsigned g_leaf[16*32];  // tree barrier leaves (128B apart)
__device__ unsigned g_root;
__device__ volatile unsigned g_gen;

// ---------------- f32x2 helpers (sm_103a packed fp32 FMA) ----------------
__device__ __forceinline__ unsigned long long ffma2(unsigned long long a,
                                                    unsigned long long b,
                                                    unsigned long long c)
{
    unsigned long long d;
    asm("fma.rn.f32x2 %0, %1, %2, %3;" : "=l"(d) : "l"(a), "l"(b), "l"(c));
    return d;
}
__device__ __forceinline__ unsigned long long splat2(float x)
{
    unsigned long long d;
    asm("mov.b64 %0, {%1, %1};" : "=l"(d) : "r"(__float_as_uint(x)));
    return d;
}
__device__ __forceinline__ float2 unpack2(unsigned long long v)
{
    float2 r;
    asm("mov.b64 {%0, %1}, %2;" : "=f"(r.x), "=f"(r.y) : "l"(v));
    return r;
}

// ---------------- 1) embedding gather + bias + threshold ----------------
__global__ void emb_kernel(const int* __restrict__ ids,
                           const float* __restrict__ W1,
                           const float* __restrict__ b1)
{
    int tok = blockIdx.x;
    int id  = ids[tok];
    for (int e = threadIdx.x; e < EHH; e += blockDim.x) {
        float v = W1[(size_t)e * VV + id] + b1[e];
        g_emb[(size_t)tok * EHH + e] = (v > 1e-6f) ? v : 0.0f;
    }
}

// ---------------- 2) tiled SGEMM (f32x2): C = act(A @ Bw^T + bias) --------
template<int ACT>
__global__ void __launch_bounds__(256)
gemm_nt_act(const float* __restrict__ A, const float* __restrict__ Bw,
            const float* __restrict__ bias, float* __restrict__ C,
            int M, int N, int K)
{
    __shared__ float As[8][132];
    __shared__ float Bs[8][132];
    const int tid = threadIdx.x;
    const int bm = blockIdx.y * 128;
    const int bn = blockIdx.x * 128;
    const int lr = tid >> 1;
    const int lc = (tid & 1) * 4;
    const int ty = tid >> 4;
    const int tx = tid & 15;

    unsigned long long acc2[4][8];
    #pragma unroll
    for (int i = 0; i < 4; i++)
        #pragma unroll
        for (int j = 0; j < 8; j++) acc2[i][j] = 0ULL;

    const float* Ap = A  + (size_t)(bm + lr) * K + lc;
    const float* Bp = Bw + (size_t)(bn + lr) * K + lc;

    for (int k0 = 0; k0 < K; k0 += 8) {
        float4 av = *(const float4*)(Ap + k0);
        float4 bv = *(const float4*)(Bp + k0);
        As[lc+0][lr] = av.x; As[lc+1][lr] = av.y;
        As[lc+2][lr] = av.z; As[lc+3][lr] = av.w;
        Bs[lc+0][lr] = bv.x; Bs[lc+1][lr] = bv.y;
        Bs[lc+2][lr] = bv.z; Bs[lc+3][lr] = bv.w;
        __syncthreads();
        #pragma unroll
        for (int kk = 0; kk < 8; kk++) {
            ulonglong2 A01 = *(const ulonglong2*)&As[kk][ty*8];
            ulonglong2 A23 = *(const ulonglong2*)&As[kk][ty*8+4];
            float4 b0 = *(const float4*)&Bs[kk][tx*8];
            float4 b1 = *(const float4*)&Bs[kk][tx*8+4];
            unsigned long long a2[4] = {A01.x, A01.y, A23.x, A23.y};
            unsigned long long bsp[8] = {
                splat2(b0.x), splat2(b0.y), splat2(b0.z), splat2(b0.w),
                splat2(b1.x), splat2(b1.y), splat2(b1.z), splat2(b1.w)};
            #pragma unroll
            for (int i2 = 0; i2 < 4; i2++)
                #pragma unroll
                for (int j = 0; j < 8; j++)
                    acc2[i2][j] = ffma2(a2[i2], bsp[j], acc2[i2][j]);
        }
        __syncthreads();
    }

    #pragma unroll
    for (int i2 = 0; i2 < 4; i2++) {
        int m0 = bm + ty*8 + i2*2;
        #pragma unroll
        for (int j = 0; j < 8; j++) {
            float2 v = unpack2(acc2[i2][j]);
            float bb = bias[bn + tx*8 + j];
            float v0 = v.x + bb, v1 = v.y + bb;
            if (ACT) { v0 = (v0 > 1e-6f) ? v0 : 0.0f;
                       v1 = (v1 > 1e-6f) ? v1 : 0.0f; }
            C[(size_t)m0     * N + bn + tx*8 + j] = v0;
            C[(size_t)(m0+1) * N + bn + tx*8 + j] = v1;
        }
    }
}

// ---------------- tree grid barrier (2-level, graph-replay safe) ----------
__device__ __forceinline__ void grid_bar()
{
    __threadfence();
    __syncthreads();
    if (threadIdx.x == 0) {
        unsigned my = g_gen;
        int leaf = blockIdx.x & 15;               // 16 leaves x 8 blocks
        bool done = false;
        if (atomicAdd(&g_leaf[leaf*32], 1) == 7) {
            g_leaf[leaf*32] = 0;
            __threadfence();                      // reset visible before release chain
            if (atomicAdd(&g_root, 1) == 15) {
                g_root = 0;
                __threadfence();
                g_gen = my + 1;
                done = true;
            }
        }
        if (!done) { while (g_gen == my) { } }
    }
    __syncthreads();
}

// ---------------- 3) persistent GRU recurrence ----------------------------
// h stored TRANSPOSED in gmem: h[j][b] (j-major). 128 blocks x 512 thr,
// 1 block/SM. Block owns 8 h-columns = 24 W_hh rows cached in smem (row
// stride 32: eight 4-aligned w-triples -> one LDS.128 per triple). 8-way K
// split; per group: double-buffered smem h tiles staged with coalesced
// LDG.128->STS.128, per-group named barriers. f32x2 FMAs.
#define WSM_F   (1024*32)          // Wsm[k*32 + tc*4 + j]
#define HSS_F   (2*8*16*68)        // Hs[buf][g][k][b] = 17408 floats
#define SMEM_BYTES ((WSM_F + HSS_F) * 4)   // 200704 B

__global__ void __launch_bounds__(GNT, 1)
gru_persist(const float* __restrict__ W_hh, const float* __restrict__ b_hh,
            const float* __restrict__ xw, float* __restrict__ hbuf)
{
    extern __shared__ float smf[];
    float* Wsm = smf;                    // 32768 floats
    float* Hss = smf + WSM_F;            // 17408 floats
    float* red = Hss;                    // alias: 8*1600 = 12800 floats

    const int tid = threadIdx.x;
    const int g   = tid >> 6;            // k-group 0..7 (covers 128 k)
    const int t   = tid & 63;
    const int tb  = t >> 3;              // batch-group 0..7 (8 batches)
    const int tc  = t & 7;               // c-group 0..7 (c = tc*3+j)
    const int j0  = blockIdx.x * 8;

    // cache W_hh slice: Wsm[k*32 + (c/3)*4 + c%3] = W_hh[(c>>3)*H + j0 + (c&7)][k]
    for (int idx = tid; idx < 24*1024; idx += GNT) {
        int c = idx >> 10, k = idx & 1023;
        int grow = (c >> 3) * HH + j0 + (c & 7);
        Wsm[k*32 + (c/3)*4 + (c%3)] = W_hh[(size_t)grow * HH + k];
    }

    // gate-phase mapping: jj slow, bb fast -> coalesced transposed h I/O
    const int jj   = tid >> 6;           // 0..7
    const int bb   = tid & 63;           // 0..63
    const int jcol = j0 + jj;
    const float bhr = b_hh[jcol];
    const float bhz = b_hh[HH + jcol];
    const float bhn = b_hh[2*HH + jcol];
    __syncthreads();

    for (int s = 0; s < SS; s++) {
        const float* h_in  = hbuf + (s & 1) * (HH*BB);
        float*       h_out = hbuf + ((s + 1) & 1) * (HH*BB);
        const float* xws   = xw + (size_t)s * BB * G3;

        // prefetch gate inputs early (hidden under the GEMM)
        float xr = __ldg(&xws[(size_t)bb*G3 + jcol]);
        float xz = __ldg(&xws[(size_t)bb*G3 + HH  + jcol]);
        float xn = __ldg(&xws[(size_t)bb*G3 + 2*HH + jcol]);
        float hp = 0.f, gr = 0.f, gz = 0.f, gn = 0.f;

        if (s > 0) {
            hp = __ldcg(&h_in[(size_t)jcol*BB + bb]);

            unsigned long long acc2[4][3];
            #pragma unroll
            for (int i = 0; i < 4; i++)
                #pragma unroll
                for (int j = 0; j < 3; j++) acc2[i][j] = 0ULL;

            // prologue: prefetch kt=0 tile (coalesced: h_in is [k][b])
            float4 pre[4];
            {
                int kb = g * 128;
                #pragma unroll
                for (int r = 0; r < 4; r++) {
                    int f = t + 64*r;          // 0..255
                    int k = kb + (f >> 4), b4 = (f & 15) * 4;
                    pre[r] = __ldcg((const float4*)&h_in[(size_t)k*BB + b4]);
                }
            }

            for (int kt = 0; kt < 8; kt++) {
                float* Hbuf = Hss + (((kt & 1) * 8 + g) * 16) * 68;
                #pragma unroll
                for (int r = 0; r < 4; r++) {
                    int f = t + 64*r;
                    int kk2 = f >> 4, b4 = (f & 15) * 4;
                    *(float4*)&Hbuf[kk2*68 + b4] = pre[r];
                }
                asm volatile("bar.sync %0, 64;" :: "r"(8 + g) : "memory");
                if (kt < 7) {
                    int kb = g * 128 + (kt + 1) * 16;
                    #pragma unroll
                    for (int r = 0; r < 4; r++) {
                        int f = t + 64*r;
                        int k = kb + (f >> 4), b4 = (f & 15) * 4;
                        pre[r] = __ldcg((const float4*)&h_in[(size_t)k*BB + b4]);
                    }
                }
                const float* wbase = Wsm + (g*128 + kt*16) * 32 + tc*4;
                #pragma unroll
                for (int kk = 0; kk < 16; kk++) {
                    const float* hrow = Hbuf + kk*68;
                    ulonglong2 hA = *(const ulonglong2*)&hrow[tb*8];
                    ulonglong2 hB = *(const ulonglong2*)&hrow[tb*8 + 4];
                    float4 wv = *(const float4*)(wbase + kk*32);
                    unsigned long long w0 = splat2(wv.x);
                    unsigned long long w1 = splat2(wv.y);
                    unsigned long long w2 = splat2(wv.z);
                    acc2[0][0] = ffma2(hA.x, w0, acc2[0][0]);
                    acc2[0][1] = ffma2(hA.x, w1, acc2[0][1]);
                    acc2[0][2] = ffma2(hA.x, w2, acc2[0][2]);
                    acc2[1][0] = ffma2(hA.y, w0, acc2[1][0]);
                    acc2[1][1] = ffma2(hA.y, w1, acc2[1][1]);
                    acc2[1][2] = ffma2(hA.y, w2, acc2[1][2]);
                    acc2[2][0] = ffma2(hB.x, w0, acc2[2][0]);
                    acc2[2][1] = ffma2(hB.x, w1, acc2[2][1]);
                    acc2[2][2] = ffma2(hB.x, w2, acc2[2][2]);
                    acc2[3][0] = ffma2(hB.y, w0, acc2[3][0]);
                    acc2[3][1] = ffma2(hB.y, w1, acc2[3][1]);
                    acc2[3][2] = ffma2(hB.y, w2, acc2[3][2]);
                }
            }

            // parallel 8-way tree reduction (partials alias Hss)
            __syncthreads();   // all groups done with Hss; reusable
            {
                float* myred = red + g * 1600;
                #pragma unroll
                for (int i2 = 0; i2 < 4; i2++) {
                    int b = tb*8 + i2*2;
                    #pragma unroll
                    for (int j = 0; j < 3; j++) {
                        float2 v = unpack2(acc2[i2][j]);
                        int c = tc*3 + j;
                        myred[b*25 + c]     = v.x;
                        myred[(b+1)*25 + c] = v.y;
                    }
                }
            }
            __syncthreads();
            for (int o = tid; o < 1600; o += GNT) {
                float sum = red[o];
                #pragma unroll
                for (int gg = 1; gg < 8; gg++) sum += red[gg*1600 + o];
                red[o] = sum;
            }
            __syncthreads();
            gr = red[bb*25 + jj];
            gz = red[bb*25 + 8 + jj];
            gn = red[bb*25 + 16 + jj];
        }

        // fused gates + h update (coalesced transposed store)
        {
            float r = 1.0f / (1.0f + __expf(-(xr + gr + bhr)));
            float z = 1.0f / (1.0f + __expf(-(xz + gz + bhz)));
            float n = tanhf(xn + r * (gn + bhn));
            __stcg(&h_out[(size_t)jcol*BB + bb], (1.0f - z) * n + z * hp);
        }

        grid_bar();
    }
}

// ---------------- zero h0 (transposed layout, same bytes) ----------------
__global__ void zero_h_kernel()
{
    int i = blockIdx.x * blockDim.x + threadIdx.x;
    ((float4*)g_h[0])[i] = make_float4(0.f, 0.f, 0.f, 0.f);
}

// ---------------- 4) final linear: out[b][n] = sum_k h[k][b]*Wo[n][k] -----
__global__ void __launch_bounds__(256)
out_kernel(const float* __restrict__ h /* [HH][BB] */,
           const float* __restrict__ Wo,
           const float* __restrict__ bo, float* __restrict__ out)
{
    __shared__ float hs[8][1032];        // [bb][k], padded stride
    const int b0 = blockIdx.x * 8;
    const int n0 = blockIdx.y * 8;
    const int tid = threadIdx.x;

    // transpose-stage: hs[bb][k] = h[k][b0+bb]
    for (int idx = tid; idx < 8192; idx += 256) {
        int k = idx >> 3, bb = idx & 7;
        hs[bb][k] = h[(size_t)k*BB + b0 + bb];
    }
    __syncthreads();

    const int w = tid >> 5, lane = tid & 31;
    const int n = n0 + w;
    float acc[8] = {0,0,0,0,0,0,0,0};
    for (int k = lane*4; k < 1024; k += 128) {
        float4 wv = *(const float4*)&Wo[(size_t)n*HH + k];
        #pragma unroll
        for (int bb = 0; bb < 8; bb++) {
            float4 hv = *(const float4*)&hs[bb][k];
            acc[bb] += wv.x*hv.x + wv.y*hv.y + wv.z*hv.z + wv.w*hv.w;
        }
    }
    #pragma unroll
    for (int bb = 0; bb < 8; bb++) {
        float v = acc[bb];
        v += __shfl_down_sync(0xffffffffu, v, 16);
        v += __shfl_down_sync(0xffffffffu, v, 8);
        v += __shfl_down_sync(0xffffffffu, v, 4);
        v += __shfl_down_sync(0xffffffffu, v, 2);
        v += __shfl_down_sync(0xffffffffu, v, 1);
        if (lane == 0) out[(size_t)(b0+bb)*1024 + n] = v + bo[n];
    }
}

// ---------------- launch ----------------
extern "C" void kernel_launch(void* const* d_in, const int* in_sizes, int n_in,
                              void* d_out, int out_size)
{
    const int*   ids   = (const int*)  d_in[0];
    const float* W1    = (const float*)d_in[1];
    const float* b1    = (const float*)d_in[2];
    const float* W2    = (const float*)d_in[3];
    const float* b2    = (const float*)d_in[4];
    const float* W_ih  = (const float*)d_in[5];
    const float* b_ih  = (const float*)d_in[6];
    const float* W_hh  = (const float*)d_in[7];
    const float* b_hh  = (const float*)d_in[8];
    const float* W_out = (const float*)d_in[9];
    const float* b_out = (const float*)d_in[10];
    float* out = (float*)d_out;

    float* emb;  cudaGetSymbolAddress((void**)&emb,  g_emb);
    float* x;    cudaGetSymbolAddress((void**)&x,    g_x);
    float* xw;   cudaGetSymbolAddress((void**)&xw,   g_xw);
    float* hbuf; cudaGetSymbolAddress((void**)&hbuf, g_h);

    static int smem_set = 0;
    if (!smem_set) {
        cudaFuncSetAttribute(gru_persist,
                             cudaFuncAttributeMaxDynamicSharedMemorySize,
                             SMEM_BYTES);
        smem_set = 1;
    }

    emb_kernel<<<TOK, 128>>>(ids, W1, b1);

    gemm_nt_act<1><<<dim3(EOO/128, TOK/128), 256>>>(emb, W2, b2, x, TOK, EOO, EHH);
    gemm_nt_act<0><<<dim3(G3/128,  TOK/128), 256>>>(x, W_ih, b_ih, xw, TOK, G3, EOO);

    zero_h_kernel<<<64, 256>>>();

    gru_persist<<<NB, GNT, SMEM_BYTES>>>(W_hh, b_hh, xw, hbuf);

    out_kernel<<<dim3(8, 128), 256>>>(hbuf, W_out, b_out, out);
}